// round 3
// baseline (speedup 1.0000x reference)
#include <cuda_runtime.h>
#include <math.h>

#define NT   8192        // tiles: bs(8) * n(32) * n(32)
#define NSM  148         // sm_100a
#define GRID (2 * NSM)   // 2 CTAs/SM persistent

static __device__ float g_P[64 * 256];     // P[pair][c], pair = m1*8+m2
static __device__ float g_A[NT * 256];     // A[t][c] = E_row(t) . W[c]

// ---------------------------------------------------------------------------
// Kernel 1: P[p][c] = sum_d pe[p][d] * W[c][d]
// ---------------------------------------------------------------------------
__global__ void compute_P_kernel(const float* __restrict__ W) {
    __shared__ float pe_row[64];
    int p = blockIdx.x;
    int c = threadIdx.x;
    if (c < 32) {
        float div = expf(-(float)c * 0.28782313662425572f);  // ln(1e4)/32
        float ang = (float)p * div;
        pe_row[2 * c]     = sinf(ang);
        pe_row[2 * c + 1] = cosf(ang);
    }
    __syncthreads();
    const float* wr = W + c * 64;
    float acc = 0.f;
#pragma unroll
    for (int d = 0; d < 64; ++d) acc += pe_row[d] * wr[d];
    g_P[p * 256 + c] = acc;
}

// ---------------------------------------------------------------------------
// Kernel 2: A[r][c] = sum_d E[r][d] * W[c][d]
// 512 blocks x 256 threads; each block does 16 rows; thread c holds W row in
// registers, E staged transposed in SMEM (broadcast LDS.128 reads).
// ---------------------------------------------------------------------------
#define AR 16
__global__ void __launch_bounds__(256) compute_A_kernel(
    const float* __restrict__ E, const float* __restrict__ W)
{
    __shared__ float Est[64 * 20];         // [d][r], stride 20 (16B aligned)
    const int tid = threadIdx.x;
    const int r0  = blockIdx.x * AR;

    for (int i = tid; i < AR * 64; i += 256) {
        int r = i >> 6, d = i & 63;
        Est[d * 20 + r] = E[(r0 + r) * 64 + d];
    }

    float4 w4[16];
    const float4* wp = (const float4*)(W + tid * 64);
#pragma unroll
    for (int i = 0; i < 16; ++i) w4[i] = wp[i];

    __syncthreads();

    float acc[AR];
#pragma unroll
    for (int r = 0; r < AR; ++r) acc[r] = 0.f;

#pragma unroll
    for (int d4 = 0; d4 < 16; ++d4) {
        float wv4[4] = {w4[d4].x, w4[d4].y, w4[d4].z, w4[d4].w};
#pragma unroll
        for (int s = 0; s < 4; ++s) {
            int d = d4 * 4 + s;
            float wv = wv4[s];
            const float4* ep = (const float4*)(Est + d * 20);
            float4 e0 = ep[0], e1 = ep[1], e2 = ep[2], e3 = ep[3];
            acc[0]  = fmaf(e0.x, wv, acc[0]);
            acc[1]  = fmaf(e0.y, wv, acc[1]);
            acc[2]  = fmaf(e0.z, wv, acc[2]);
            acc[3]  = fmaf(e0.w, wv, acc[3]);
            acc[4]  = fmaf(e1.x, wv, acc[4]);
            acc[5]  = fmaf(e1.y, wv, acc[5]);
            acc[6]  = fmaf(e1.z, wv, acc[6]);
            acc[7]  = fmaf(e1.w, wv, acc[7]);
            acc[8]  = fmaf(e2.x, wv, acc[8]);
            acc[9]  = fmaf(e2.y, wv, acc[9]);
            acc[10] = fmaf(e2.z, wv, acc[10]);
            acc[11] = fmaf(e2.w, wv, acc[11]);
            acc[12] = fmaf(e3.x, wv, acc[12]);
            acc[13] = fmaf(e3.y, wv, acc[13]);
            acc[14] = fmaf(e3.z, wv, acc[14]);
            acc[15] = fmaf(e3.w, wv, acc[15]);
        }
    }
#pragma unroll
    for (int r = 0; r < AR; ++r) g_A[(r0 + r) * 256 + tid] = acc[r];
}

// ---------------------------------------------------------------------------
// Kernel 3: persistent pure-store kernel. No SMEM, no barriers.
// out[b, i1*8+m1, j1*8+m2, c] = m1v*m2v * (A[t][c] + P[m1*8+m2][c])
// Thread: cq = tid&63 (4 c-values), grp = tid>>6 -> m2 in {grp, grp+4}.
// P slice held in 16 float4 registers.
// ---------------------------------------------------------------------------
__global__ void __launch_bounds__(256, 2) etoc_store_kernel(
    const float* __restrict__ m1g,
    const float* __restrict__ m2g,
    float4* __restrict__ out4)
{
    const int tid = threadIdx.x;
    const int cq  = tid & 63;
    const int grp = tid >> 6;

    float4 Pr[16];
#pragma unroll
    for (int m1 = 0; m1 < 8; ++m1) {
#pragma unroll
        for (int s = 0; s < 2; ++s) {
            Pr[m1 * 2 + s] =
                *(const float4*)(g_P + (m1 * 8 + grp + 4 * s) * 256 + 4 * cq);
        }
    }

    for (int t = blockIdx.x; t < NT; t += GRID) {
        int b  = t >> 10;
        int i1 = (t >> 5) & 31;
        int j1 = t & 31;

        float4 a4  = *(const float4*)(g_A + t * 256 + 4 * cq);
        float  m1v = __ldg(m1g + b * 32 + i1);
        float  m2a = __ldg(m2g + b * 32 + ((j1 * 8 + grp) & 31));
        float  m2b = __ldg(m2g + b * 32 + ((j1 * 8 + grp + 4) & 31));
        float  fa  = m1v * m2a;
        float  fb  = m1v * m2b;

        float4 aa = {fa * a4.x, fa * a4.y, fa * a4.z, fa * a4.w};
        float4 ab = {fb * a4.x, fb * a4.y, fb * a4.z, fb * a4.w};

        float4* p0 = out4 +
            (((long)(b * 256 + i1 * 8) * 256) + j1 * 8 + grp) * 64 + cq;

#pragma unroll
        for (int m1 = 0; m1 < 8; ++m1) {
            float4 pa = Pr[2 * m1];
            float4 va;
            va.x = fmaf(fa, pa.x, aa.x);
            va.y = fmaf(fa, pa.y, aa.y);
            va.z = fmaf(fa, pa.z, aa.z);
            va.w = fmaf(fa, pa.w, aa.w);
            __stcs(p0 + m1 * 16384, va);

            float4 pb = Pr[2 * m1 + 1];
            float4 vb;
            vb.x = fmaf(fb, pb.x, ab.x);
            vb.y = fmaf(fb, pb.y, ab.y);
            vb.z = fmaf(fb, pb.z, ab.z);
            vb.w = fmaf(fb, pb.w, ab.w);
            __stcs(p0 + m1 * 16384 + 256, vb);
        }
    }
}

// ---------------------------------------------------------------------------
// Launch
// ---------------------------------------------------------------------------
extern "C" void kernel_launch(void* const* d_in, const int* in_sizes, int n_in,
                              void* d_out, int out_size) {
    const float* E  = (const float*)d_in[0];  // (8,32,32,64)
    const float* m1 = (const float*)d_in[1];  // (8,32,1,1)
    const float* m2 = (const float*)d_in[2];  // (8,1,32,1)
    const float* W  = (const float*)d_in[3];  // (256,64)

    compute_P_kernel<<<64, 256>>>(W);
    compute_A_kernel<<<NT / AR, 256>>>(E, W);
    etoc_store_kernel<<<GRID, 256>>>(m1, m2, (float4*)d_out);
}

// round 7
// speedup vs baseline: 1.0656x; 1.0656x over previous
#include <cuda_runtime.h>
#include <math.h>

#define NT   8192        // tiles: bs(8) * n(32) * n(32)
#define NSM  148         // sm_100a
#define GRID (2 * NSM)   // 2 CTAs/SM persistent

static __device__ float g_P[64 * 256];     // P[pair][c], pair = m1*8+m2
static __device__ float g_A[NT * 256];     // A[t][c] = E_row(t) . W[c]

// ---------------------------------------------------------------------------
// Kernel 1 (prep): blocks 0..511 compute A, blocks 512..575 compute P.
//
// A: A[r][c] = sum_d E[r][d] * W[c][d]; 16 rows/block, E staged transposed
//    in SMEM, W row in registers (16 independent float4 loads).
// P: P[p][c] = sum_d pe[p][d] * W[c][d]; pe row in SMEM, W row in registers,
//    4 accumulator chains (no serial LDG->FFMA dependency).
// ---------------------------------------------------------------------------
#define AR 16
__global__ void __launch_bounds__(256) prep_kernel(
    const float* __restrict__ E, const float* __restrict__ W)
{
    __shared__ float sh[64 * 20];          // A: Est[d][r] stride 20; P: pe row
    const int tid = threadIdx.x;

    // W row for this thread's c: 16 independent vector loads (both roles)
    float4 w4[16];
    const float4* wp = (const float4*)(W + tid * 64);
#pragma unroll
    for (int i = 0; i < 16; ++i) w4[i] = wp[i];

    if (blockIdx.x < 512) {
        const int r0 = blockIdx.x * AR;
        for (int i = tid; i < AR * 64; i += 256) {
            int r = i >> 6, d = i & 63;
            sh[d * 20 + r] = E[(r0 + r) * 64 + d];
        }
        __syncthreads();

        float acc[AR];
#pragma unroll
        for (int r = 0; r < AR; ++r) acc[r] = 0.f;

#pragma unroll
        for (int d4 = 0; d4 < 16; ++d4) {
            float wv4[4] = {w4[d4].x, w4[d4].y, w4[d4].z, w4[d4].w};
#pragma unroll
            for (int s = 0; s < 4; ++s) {
                int d = d4 * 4 + s;
                float wv = wv4[s];
                const float4* ep = (const float4*)(sh + d * 20);
                float4 e0 = ep[0], e1 = ep[1], e2 = ep[2], e3 = ep[3];
                acc[0]  = fmaf(e0.x, wv, acc[0]);
                acc[1]  = fmaf(e0.y, wv, acc[1]);
                acc[2]  = fmaf(e0.z, wv, acc[2]);
                acc[3]  = fmaf(e0.w, wv, acc[3]);
                acc[4]  = fmaf(e1.x, wv, acc[4]);
                acc[5]  = fmaf(e1.y, wv, acc[5]);
                acc[6]  = fmaf(e1.z, wv, acc[6]);
                acc[7]  = fmaf(e1.w, wv, acc[7]);
                acc[8]  = fmaf(e2.x, wv, acc[8]);
                acc[9]  = fmaf(e2.y, wv, acc[9]);
                acc[10] = fmaf(e2.z, wv, acc[10]);
                acc[11] = fmaf(e2.w, wv, acc[11]);
                acc[12] = fmaf(e3.x, wv, acc[12]);
                acc[13] = fmaf(e3.y, wv, acc[13]);
                acc[14] = fmaf(e3.z, wv, acc[14]);
                acc[15] = fmaf(e3.w, wv, acc[15]);
            }
        }
#pragma unroll
        for (int r = 0; r < AR; ++r) g_A[(r0 + r) * 256 + tid] = acc[r];
    } else {
        const int p = blockIdx.x - 512;
        if (tid < 32) {
            float div = expf(-(float)tid * 0.28782313662425572f); // ln(1e4)/32
            float ang = (float)p * div;
            sh[2 * tid]     = sinf(ang);
            sh[2 * tid + 1] = cosf(ang);
        }
        __syncthreads();

        float a0 = 0.f, a1 = 0.f, a2 = 0.f, a3 = 0.f;
#pragma unroll
        for (int i = 0; i < 16; ++i) {
            a0 = fmaf(sh[4 * i + 0], w4[i].x, a0);
            a1 = fmaf(sh[4 * i + 1], w4[i].y, a1);
            a2 = fmaf(sh[4 * i + 2], w4[i].z, a2);
            a3 = fmaf(sh[4 * i + 3], w4[i].w, a3);
        }
        g_P[p * 256 + tid] = (a0 + a1) + (a2 + a3);
    }
}

// ---------------------------------------------------------------------------
// Kernel 2: persistent pure-store kernel. No SMEM, no barriers.
// Software-pipelined: next tile's A row + masks are loaded before the
// current tile's 16 streaming stores, hiding L2 latency behind store issue.
// ---------------------------------------------------------------------------
__global__ void __launch_bounds__(256, 2) etoc_store_kernel(
    const float* __restrict__ m1g,
    const float* __restrict__ m2g,
    float4* __restrict__ out4)
{
    const int tid = threadIdx.x;
    const int cq  = tid & 63;
    const int grp = tid >> 6;

    float4 Pr[16];
#pragma unroll
    for (int m1 = 0; m1 < 8; ++m1) {
#pragma unroll
        for (int s = 0; s < 2; ++s) {
            Pr[m1 * 2 + s] =
                *(const float4*)(g_P + (m1 * 8 + grp + 4 * s) * 256 + 4 * cq);
        }
    }

    int t = blockIdx.x;
    if (t >= NT) return;

    // Prologue loads for first tile
    int b  = t >> 10, i1 = (t >> 5) & 31, j1 = t & 31;
    float4 a4  = *(const float4*)(g_A + t * 256 + 4 * cq);
    float  m1v = __ldg(m1g + b * 32 + i1);
    float  m2a = __ldg(m2g + b * 32 + ((j1 * 8 + grp) & 31));
    float  m2b = __ldg(m2g + b * 32 + ((j1 * 8 + grp + 4) & 31));

    while (true) {
        // Prefetch next tile
        int tn = t + GRID;
        float4 a4n;
        float  m1n = 0.f, m2an = 0.f, m2bn = 0.f;
        bool   more = tn < NT;
        if (more) {
            int bn = tn >> 10, i1n = (tn >> 5) & 31, j1n = tn & 31;
            a4n  = *(const float4*)(g_A + tn * 256 + 4 * cq);
            m1n  = __ldg(m1g + bn * 32 + i1n);
            m2an = __ldg(m2g + bn * 32 + ((j1n * 8 + grp) & 31));
            m2bn = __ldg(m2g + bn * 32 + ((j1n * 8 + grp + 4) & 31));
        }

        // Compute + store current tile (64 KB per CTA)
        float fa = m1v * m2a;
        float fb = m1v * m2b;
        float4 aa = {fa * a4.x, fa * a4.y, fa * a4.z, fa * a4.w};
        float4 ab = {fb * a4.x, fb * a4.y, fb * a4.z, fb * a4.w};

        float4* p0 = out4 +
            ((unsigned)(b * 256 + i1 * 8) * 256u + (unsigned)(j1 * 8 + grp)) * 64u
            + (unsigned)cq;

#pragma unroll
        for (int m1 = 0; m1 < 8; ++m1) {
            float4 pa = Pr[2 * m1];
            float4 va;
            va.x = fmaf(fa, pa.x, aa.x);
            va.y = fmaf(fa, pa.y, aa.y);
            va.z = fmaf(fa, pa.z, aa.z);
            va.w = fmaf(fa, pa.w, aa.w);
            __stcs(p0 + m1 * 16384, va);

            float4 pb = Pr[2 * m1 + 1];
            float4 vb;
            vb.x = fmaf(fb, pb.x, ab.x);
            vb.y = fmaf(fb, pb.y, ab.y);
            vb.z = fmaf(fb, pb.z, ab.z);
            vb.w = fmaf(fb, pb.w, ab.w);
            __stcs(p0 + m1 * 16384 + 256, vb);
        }

        if (!more) break;
        t = tn;
        b = t >> 10; i1 = (t >> 5) & 31; j1 = t & 31;
        a4 = a4n; m1v = m1n; m2a = m2an; m2b = m2bn;
    }
}

// ---------------------------------------------------------------------------
// Launch
// ---------------------------------------------------------------------------
extern "C" void kernel_launch(void* const* d_in, const int* in_sizes, int n_in,
                              void* d_out, int out_size) {
    const float* E  = (const float*)d_in[0];  // (8,32,32,64)
    const float* m1 = (const float*)d_in[1];  // (8,32,1,1)
    const float* m2 = (const float*)d_in[2];  // (8,1,32,1)
    const float* W  = (const float*)d_in[3];  // (256,64)

    prep_kernel<<<512 + 64, 256>>>(E, W);
    etoc_store_kernel<<<GRID, 256>>>(m1, m2, (float4*)d_out);
}